// round 10
// baseline (speedup 1.0000x reference)
#include <cuda_runtime.h>
#include <cuda_bf16.h>

// Problem constants
#define KK 8      // slots
#define VV 256    // vocab
#define TT 11     // time
#define NN 8      // scanner neurons
#define HH 255    // hidden per slot
#define BB 2048   // batch

#define VS 16             // v segments per block
#define VLEN 8            // v values per thread
#define VHALF 128         // v values per block (2 blocks per batch element)
#define TK4 22            // float4 chunks per (b, v): 88 floats / 4
#define NTHR (VS * TK4)   // 352 threads per block

// Precomputed per-(k,v) contribution to the two output channels, with the
// output bias folded in as bias/8 per slot. 8*256 float2 = 16 KB.
__device__ float2 g_table[KK * VV];

// ----------------------------------------------------------------------------
// Kernel 1 (PDL primary): build
//   G'[o,k,v] = out_b[o]/8 + sum_h out_w[o, k*255+h] *
//               relu( sum_n hidden_w[k*255+h, n] * relu(scanner_w[n,v,k]) )
// One warp per (k, v). Also zero-initializes the output buffer (the stream
// kernel accumulates into it with atomics). Triggers the dependent stream
// kernel's launch immediately — its epilogue grid-dep-syncs on us anyway.
// ----------------------------------------------------------------------------
__global__ void precompute_table(const float* __restrict__ scanner_w,   // (N, V, K)
                                 const float* __restrict__ hidden_w,    // (K*H, N)
                                 const float* __restrict__ out_w,       // (2, K*H)
                                 const float* __restrict__ out_b,       // (2,)
                                 float* __restrict__ out) {             // (B, 2, T)
    cudaTriggerProgrammaticLaunchCompletion();   // let the stream kernel ramp now

    int gtid = blockIdx.x * blockDim.x + threadIdx.x;   // 65536 threads
    if (gtid < BB * 2 * TT) out[gtid] = 0.f;            // zero-init for atomics

    int warp = gtid >> 5;
    int lane = threadIdx.x & 31;
    if (warp >= KK * VV) return;
    int k = warp >> 8;      // 0..7
    int v = warp & 255;     // 0..255

    float s[NN];
#pragma unroll
    for (int n = 0; n < NN; n++) {
        float w = __ldg(&scanner_w[n * (VV * KK) + v * KK + k]);
        s[n] = w > 0.f ? w : 0.f;
    }

    float g0 = 0.f, g1 = 0.f;
#pragma unroll
    for (int j = 0; j < 8; j++) {
        int h = lane + j * 32;
        if (h < HH) {
            int c = k * HH + h;
            const float4* hw = (const float4*)(hidden_w + c * NN);
            float4 w0 = hw[0];
            float4 w1 = hw[1];
            float acc = w0.x * s[0] + w0.y * s[1] + w0.z * s[2] + w0.w * s[3]
                      + w1.x * s[4] + w1.y * s[5] + w1.z * s[6] + w1.w * s[7];
            float a = acc > 0.f ? acc : 0.f;
            g0 = fmaf(a, __ldg(&out_w[c]), g0);
            g1 = fmaf(a, __ldg(&out_w[KK * HH + c]), g1);
        }
    }
#pragma unroll
    for (int off = 16; off > 0; off >>= 1) {
        g0 += __shfl_xor_sync(0xffffffffu, g0, off);
        g1 += __shfl_xor_sync(0xffffffffu, g1, off);
    }
    if (lane == 0) {
        // fold bias/8 into each slot entry (8 slots sum to exactly 1x bias)
        g_table[k * VV + v] = make_float2(g0 + 0.125f * __ldg(&out_b[0]),
                                          g1 + 0.125f * __ldg(&out_b[1]));
    }
}

// ----------------------------------------------------------------------------
// Kernel 2 (PDL secondary): stream x_unfolded (B, V, T, K). Two blocks per
// batch element, each covering 128 v values. 352 threads = 22 tk4-chunks x
// 16 v-segments; each thread scans only 8 v values (stride 88 floats), so
// T_block is ~5.8us and the end-of-grid bandwidth ramp-down tail is half of
// the previous 176-thread/16-iteration layout. Occupancy is unchanged:
// 11 warp-slots x 5 blocks/SM = 55 warps (85.9% theoretical).
//
// The DRAM-bound load loop runs BEFORE cudaGridDependencySynchronize,
// overlapping with the precompute kernel; only the table-lookup epilogue
// waits for it.
//
// One-hot structure: each (t,k) column has exactly one v with value 1.0, so
// a partial scan yields w in {0,1} and (when w=1) f = sum(val*i) recovers the
// index as id = f + vbase*w. Per-t partials reduce deterministically in smem;
// the two blocks of a batch element combine via one atomicAdd each (2
// commutative float adds onto a zeroed cell -> bit-deterministic).
// ----------------------------------------------------------------------------
__global__ void __launch_bounds__(NTHR, 5)
scanner_stream(const float* __restrict__ x,
               float* __restrict__ out) {            // (B, 2, T)
    int b     = blockIdx.x >> 1;
    int vhalf = blockIdx.x & 1;
    int tid   = threadIdx.x;          // 0..351
    int vseg  = tid / TK4;            // 0..15
    int tk4   = tid - vseg * TK4;     // 0..21
    int vbase = vhalf * VHALF + vseg * VLEN;

    const float4* base = (const float4*)(x + (size_t)b * (VV * TT * KK))
                         + (size_t)vbase * TK4 + tk4;

    float f0 = 0.f, f1 = 0.f, f2 = 0.f, f3 = 0.f;   // sum val * i (i immediate)
    float w0 = 0.f, w1 = 0.f, w2 = 0.f, w3 = 0.f;   // sum val (0 or 1)
#pragma unroll
    for (int i = 0; i < VLEN; i++) {
        float4 val = __ldcs(&base[i * TK4]);        // 352B stride, streaming
        float fi = (float)i;                        // compile-time immediate
        f0 = fmaf(val.x, fi, f0);  w0 += val.x;
        f1 = fmaf(val.y, fi, f1);  w1 += val.y;
        f2 = fmaf(val.z, fi, f2);  w2 += val.z;
        f3 = fmaf(val.w, fi, f3);  w3 += val.w;
    }

    // Wait for precompute (g_table + out zero-init) only now.
    cudaGridDependencySynchronize();

    // per-thread table lookups (id exact: one-hot value is exactly 1.0)
    float vb = (float)vbase;
    int kbase = (tk4 & 1) * 4;       // even chunk -> k0..3, odd -> k4..7
    float s0 = 0.f, s1 = 0.f;
    int id;
    float2 g;
    id = (int)(fmaf(vb, w0, f0) + 0.5f); g = g_table[(kbase + 0) * VV + id];
    s0 = fmaf(w0, g.x, s0); s1 = fmaf(w0, g.y, s1);
    id = (int)(fmaf(vb, w1, f1) + 0.5f); g = g_table[(kbase + 1) * VV + id];
    s0 = fmaf(w1, g.x, s0); s1 = fmaf(w1, g.y, s1);
    id = (int)(fmaf(vb, w2, f2) + 0.5f); g = g_table[(kbase + 2) * VV + id];
    s0 = fmaf(w2, g.x, s0); s1 = fmaf(w2, g.y, s1);
    id = (int)(fmaf(vb, w3, f3) + 0.5f); g = g_table[(kbase + 3) * VV + id];
    s0 = fmaf(w3, g.x, s0); s1 = fmaf(w3, g.y, s1);

    __shared__ float2 ss[VS][TK4];
    ss[vseg][tk4] = make_float2(s0, s1);
    __syncthreads();

    if (tid < TK4) {                  // lanes 0..21 of warp 0
        float a0 = 0.f, a1 = 0.f;
#pragma unroll
        for (int s = 0; s < VS; s++) {   // fixed order -> deterministic
            float2 p = ss[s][tid];
            a0 += p.x; a1 += p.y;
        }
        // merge k0..3 half (even lane) with k4..7 half (odd lane)
        const unsigned mask = 0x003FFFFFu;
        a0 += __shfl_xor_sync(mask, a0, 1);
        a1 += __shfl_xor_sync(mask, a1, 1);

        if ((tid & 1) == 0) {
            int t = tid >> 1;
            atomicAdd(&out[b * (2 * TT) + t],      a0);
            atomicAdd(&out[b * (2 * TT) + TT + t], a1);
        }
    }
}

extern "C" void kernel_launch(void* const* d_in, const int* in_sizes, int n_in,
                              void* d_out, int out_size) {
    const float* x         = (const float*)d_in[0];   // (B, V, T, K)  46137344
    const float* scanner_w = (const float*)d_in[1];   // (N, V, K)     16384
    const float* hidden_w  = (const float*)d_in[2];   // (K*H, N)      16320
    const float* out_w     = (const float*)d_in[3];   // (2, K*H)      4080
    const float* out_bias  = (const float*)d_in[4];   // (2,)          2
    float* out = (float*)d_out;                       // (B, 2, T)     45056

    precompute_table<<<256, 256>>>(scanner_w, hidden_w, out_w, out_bias, out);

    // Secondary launch with programmatic dependent launch: its load loop
    // overlaps the precompute kernel; epilogue grid-dep-syncs before using
    // g_table / out.
    cudaLaunchConfig_t cfg = {};
    cfg.gridDim  = dim3(2 * BB);
    cfg.blockDim = dim3(NTHR);
    cfg.dynamicSmemBytes = 0;
    cfg.stream = 0;
    cudaLaunchAttribute attrs[1];
    attrs[0].id = cudaLaunchAttributeProgrammaticStreamSerialization;
    attrs[0].val.programmaticStreamSerializationAllowed = 1;
    cfg.attrs = attrs;
    cfg.numAttrs = 1;
    cudaLaunchKernelEx(&cfg, scanner_stream, x, out);
}